// round 12
// baseline (speedup 1.0000x reference)
#include <cuda_runtime.h>

#define BATCH 16
#define CH    256
#define IH    100
#define IW    100
#define NBOX  100
#define RH    40
#define RW    40
#define NCLS  599
#define CPB   2          // channels per CTA in resize/pool kernel (known-good)
#define CTAS_PER_B (CH / CPB)                   // 128
#define OUT_ELEMS (BATCH * NCLS * CH)           // 2,453,504 floats
#define OUT_F4    (OUT_ELEMS / 4)               // 613,376 float4

// Scratch (no allocations allowed)
__device__ float g_pooled[BATCH * NBOX * CH];   // [B][N][C]
__device__ int   g_start[BATCH * (NCLS + 1)];   // class -> start offset in g_list
__device__ int   g_list[BATCH * NBOX];          // box idx sorted by class (asc n within)
__device__ int   g_scls[BATCH * NBOX];          // class at each sorted position
__device__ int   g_arrive[BATCH];               // zero-init; reset by finisher each launch

// Quantize one box (xyxy, image coords) to the 40x40 grid. Matches
// jnp.round (half-to-even) + clip semantics of the reference.
__device__ __forceinline__ int quantize_box(float4 bb, bool& valid) {
    const float s = 40.0f / 1024.0f;            // exact in fp32
    int x1 = max((int)rintf(bb.x * s), 0);
    int y1 = max((int)rintf(bb.y * s), 0);
    int x2 = min((int)rintf(bb.z * s), RW);
    int y2 = min((int)rintf(bb.w * s), RH);
    valid = (x1 < x2) && (y1 < y2);
    x1 = min(max(x1, 0), RW);  x2 = min(max(x2, 0), RW);
    y1 = min(max(y1, 0), RH);  y2 = min(max(y2, 0), RH);
    return x1 | (y1 << 8) | (x2 << 16) | (y2 << 24);
}

// ---------------------------------------------------------------------------
// Kernel 0: zero-fill the output. Pure store stream (no loads, no barriers).
// ---------------------------------------------------------------------------
__global__ __launch_bounds__(256) void zero_kernel(float* __restrict__ out) {
    int i = blockIdx.x * 256 + threadIdx.x;
    if (i < OUT_F4)
        ((float4*)out)[i] = make_float4(0.0f, 0.0f, 0.0f, 0.0f);
}

// ---------------------------------------------------------------------------
// Kernel 1: per (b, 2 channels) — direct-__ldg bilinear 100->40 resize into
// smem, then direct box-sum pooling. cbas==0 CTA also counting-sorts boxes by
// class. Epilogue: per-batch arrival counter; the 128th arriving CTA of each
// batch (all batch data now globally visible) computes the per-class means
// for the whole batch — its 8 warps take segments k ≡ warp (mod 8) of the
// presorted list, each summing rows in ascending-n (segment_sum) order.
// ---------------------------------------------------------------------------
__global__ __launch_bounds__(256) void resize_pool_kernel(
        const float* __restrict__ feat, const float* __restrict__ boxes,
        const int* __restrict__ gt, float* __restrict__ out) {
    __shared__ float res[CPB][RH * RW];         // 12.8 KB
    __shared__ int   s_box[NBOX];               // packed x1,y1,x2,y2 (0 if invalid)
    __shared__ float s_pool[NBOX][CPB];         // staged for float2 writes
    __shared__ int   s_cls[NBOX];               // valid ? cls : -1 (meta CTA)
    __shared__ int   s_cnt[NCLS];               // histogram -> offsets (meta CTA)
    __shared__ int   s_blk[20];
    __shared__ int   s_arr;

    const int blk  = blockIdx.x;                // 0 .. BATCH*CTAS_PER_B-1
    const int b    = blk / CTAS_PER_B;
    const int cbas = (blk % CTAS_PER_B) * CPB;
    const int tid  = threadIdx.x;
    const bool meta = (cbas == 0);              // uniform across CTA

    // --- quantize this batch's boxes (threads 0..99) ---
    bool v_me = false;
    if (tid < NBOX) {
        float4 bb = __ldg((const float4*)boxes + b * NBOX + tid);
        int pk = quantize_box(bb, v_me);
        s_box[tid] = v_me ? pk : 0;             // invalid -> x1==x2==0
        if (meta) {
            int cls = __ldg(gt + b * NBOX + tid);
            s_cls[tid] = v_me ? cls : -1;
        }
    }

    // --- bilinear resize (half-pixel centers): src = 2.5*dst + 0.75 ---
    const float* __restrict__ in0 = feat + (size_t)(b * CH + cbas) * (IH * IW);
    const float* __restrict__ in1 = in0 + IH * IW;
    for (int i = tid; i < RH * RW; i += 256) {
        int oy = i / RW, ox = i % RW;
        float sy = 2.5f * (float)oy + 0.75f;    // frac is exactly .75 or .25
        float sx = 2.5f * (float)ox + 0.75f;
        int y0 = (int)sy;  float fy = sy - (float)y0;
        int x0 = (int)sx;  float fx = sx - (float)x0;
        int off = y0 * IW + x0;
        float gx0 = 1.0f - fx, gy0 = 1.0f - fy;
        float a00 = __ldg(in0 + off),      a01 = __ldg(in0 + off + 1);
        float a10 = __ldg(in0 + off + IW), a11 = __ldg(in0 + off + IW + 1);
        float b00 = __ldg(in1 + off),      b01 = __ldg(in1 + off + 1);
        float b10 = __ldg(in1 + off + IW), b11 = __ldg(in1 + off + IW + 1);
        res[0][i] = gy0 * (gx0 * a00 + fx * a01) + fy * (gx0 * a10 + fx * a11);
        res[1][i] = gy0 * (gx0 * b00 + fx * b01) + fy * (gx0 * b10 + fx * b11);
    }
    __syncthreads();

    // --- direct box-average pooling: thread = (plane, box) ---
    if (tid < NBOX * CPB) {
        int n = tid % NBOX;
        int p = tid / NBOX;
        int pk = s_box[n];
        int x1 = pk & 0xFF, y1 = (pk >> 8) & 0xFF;
        int x2 = (pk >> 16) & 0xFF, y2 = (pk >> 24) & 0xFF;
        float out_v = 0.0f;
        if (x1 < x2) {                          // valid (invalid stored as 0)
            float s = 0.0f;
            const float* r = res[p];
            for (int y = y1; y < y2; y++) {
                float rs = 0.0f;
                for (int x = x1; x < x2; x++) rs += r[y * RW + x];
                s += rs;
            }
            out_v = s / (float)((y2 - y1) * (x2 - x1));
        }
        s_pool[n][p] = out_v;
    }
    __syncthreads();

    // --- transposed write: one float2 per box into [B][N][C] ---
    if (tid < NBOX) {
        float2 v2 = make_float2(s_pool[tid][0], s_pool[tid][1]);
        *(float2*)(g_pooled + (size_t)(b * NBOX + tid) * CH + cbas) = v2;
    }

    // --- meta CTA only: counting-sort boxes by class (deterministic) ---
    if (meta) {
        for (int i = tid; i < NCLS; i += 256) s_cnt[i] = 0;
        __syncthreads();
        if (tid < NBOX && s_cls[tid] >= 0)
            atomicAdd(&s_cnt[s_cls[tid]], 1);   // histogram
        __syncthreads();
        if (tid < 19) {                          // group sums (19 x 32)
            int s = 0;
            for (int j = 0; j < 32; j++) {
                int c = tid * 32 + j;
                if (c < NCLS) s += s_cnt[c];
            }
            s_blk[tid] = s;
        }
        __syncthreads();
        if (tid == 0) {
            int r = 0;
            for (int w = 0; w < 19; w++) { int t = s_blk[w]; s_blk[w] = r; r += t; }
            s_blk[19] = r;                      // total valid boxes
        }
        __syncthreads();
        if (tid < 19) {
            int r = s_blk[tid];
            for (int j = 0; j < 32; j++) {
                int c = tid * 32 + j;
                if (c < NCLS) { int t = s_cnt[c]; s_cnt[c] = r; r += t; }  // -> offsets
            }
        }
        __syncthreads();
        for (int i = tid; i < NCLS; i += 256)
            g_start[b * (NCLS + 1) + i] = s_cnt[i];
        if (tid == 0)
            g_start[b * (NCLS + 1) + NCLS] = s_blk[19];
        // scatter: rank = #{m<n with same class} (deterministic ascending order)
        if (tid < NBOX && s_cls[tid] >= 0) {
            int c = s_cls[tid];
            int rank = 0;
            for (int m = 0; m < tid; m++) rank += (s_cls[m] == c);
            int pos = s_cnt[c] + rank;
            g_list[b * NBOX + pos] = tid;
            g_scls[b * NBOX + pos] = c;
        }
    }

    // --- arrival: last CTA of this batch becomes the finisher ---
    __syncthreads();                            // all smem/global work issued
    __threadfence();                            // make this CTA's writes visible
    if (tid == 0) s_arr = atomicAdd(&g_arrive[b], 1);
    __syncthreads();
    if (s_arr != CTAS_PER_B - 1) return;        // not the finisher

    // Finisher: all 128 CTAs of batch b have arrived -> data visible.
    __threadfence();                            // acquire side
    if (tid == 0) g_arrive[b] = 0;              // reset for next graph replay

    const int total = __ldg(&g_start[b * (NCLS + 1) + NCLS]);
    const int wid  = tid >> 5;                  // warp = independent segment slice
    const int lane = tid & 31;
    const int* sb = &g_start[b * (NCLS + 1)];

    for (int k = wid; k < total; k += 8) {
        int cls = __ldg(&g_scls[b * NBOX + k]);
        int st  = __ldg(sb + cls);
        if (k != st) continue;                  // not a segment head
        int en  = __ldg(sb + cls + 1);
        float4 a0 = make_float4(0.f, 0.f, 0.f, 0.f);
        float4 a1 = make_float4(0.f, 0.f, 0.f, 0.f);
        for (int j = st; j < en; j++) {         // ascending n within class
            int n = __ldg(&g_list[b * NBOX + j]);
            const float4* row = (const float4*)(g_pooled + (size_t)(b * NBOX + n) * CH);
            float4 v0 = __ldg(row + lane);
            float4 v1 = __ldg(row + lane + 32);
            a0.x += v0.x; a0.y += v0.y; a0.z += v0.z; a0.w += v0.w;
            a1.x += v1.x; a1.y += v1.y; a1.z += v1.z; a1.w += v1.w;
        }
        float inv = 1.0f / (float)(en - st);
        a0.x *= inv; a0.y *= inv; a0.z *= inv; a0.w *= inv;
        a1.x *= inv; a1.y *= inv; a1.z *= inv; a1.w *= inv;
        float4* o = (float4*)(out + (size_t)(b * NCLS + cls) * CH);
        o[lane]      = a0;
        o[lane + 32] = a1;
    }
}

// ---------------------------------------------------------------------------
extern "C" void kernel_launch(void* const* d_in, const int* in_sizes, int n_in,
                              void* d_out, int out_size) {
    const float* feat  = (const float*)d_in[0];   // [16,256,100,100] f32
    const float* boxes = (const float*)d_in[1];   // [16,100,4] f32
    const int*   gt    = (const int*)d_in[2];     // [16,100] i32
    float* out = (float*)d_out;                   // [16,599,256] f32

    zero_kernel<<<(OUT_F4 + 255) / 256, 256>>>(out);
    resize_pool_kernel<<<BATCH * CTAS_PER_B, 256>>>(feat, boxes, gt, out);
}

// round 13
// speedup vs baseline: 1.4195x; 1.4195x over previous
#include <cuda_runtime.h>

#define BATCH 16
#define CH    256
#define IH    100
#define IW    100
#define NBOX  100
#define RH    40
#define RW    40
#define NCLS  599
#define CPB   2          // channels per CTA in resize/pool kernel (known-good)

// Scratch (no allocations allowed)
__device__ float g_pooled[BATCH * NBOX * CH];   // [B][N][C]  (coalesced reads in k2)
__device__ int   g_start[BATCH * (NCLS + 1)];   // class -> start offset in g_list
__device__ int   g_list[BATCH * NBOX];          // box idx sorted by class (asc n within)

// Quantize one box (xyxy, image coords) to the 40x40 grid. Matches
// jnp.round (half-to-even) + clip semantics of the reference.
__device__ __forceinline__ int quantize_box(float4 bb, bool& valid) {
    const float s = 40.0f / 1024.0f;            // exact in fp32
    int x1 = max((int)rintf(bb.x * s), 0);
    int y1 = max((int)rintf(bb.y * s), 0);
    int x2 = min((int)rintf(bb.z * s), RW);
    int y2 = min((int)rintf(bb.w * s), RH);
    valid = (x1 < x2) && (y1 < y2);
    x1 = min(max(x1, 0), RW);  x2 = min(max(x2, 0), RW);
    y1 = min(max(y1, 0), RH);  y2 = min(max(y2, 0), RH);
    return x1 | (y1 << 8) | (x2 << 16) | (y2 << 24);
}

// ---------------------------------------------------------------------------
// Kernel 1 (R10-measured best, ~27.6us): per (b, 2 channels) — direct-__ldg
// bilinear 100->40 resize into smem, then direct box-sum pooling. The cbas==0
// CTA of each batch also counting-sorts boxes by class into g_start / g_list
// (deterministic, ascending-n within each class).
// ---------------------------------------------------------------------------
__global__ __launch_bounds__(256) void resize_pool_kernel(
        const float* __restrict__ feat, const float* __restrict__ boxes,
        const int* __restrict__ gt) {
    __shared__ float res[CPB][RH * RW];         // 12.8 KB
    __shared__ int   s_box[NBOX];               // packed x1,y1,x2,y2 (0 if invalid)
    __shared__ float s_pool[NBOX][CPB];         // staged for float2 writes
    __shared__ int   s_cls[NBOX];               // valid ? cls : -1 (meta CTA)
    __shared__ int   s_cnt[NCLS];               // histogram -> offsets (meta CTA)
    __shared__ int   s_blk[20];

    const int blk  = blockIdx.x;                // 0 .. BATCH*CH/CPB-1
    const int b    = blk / (CH / CPB);
    const int cbas = (blk % (CH / CPB)) * CPB;
    const int tid  = threadIdx.x;
    const bool meta = (cbas == 0);              // uniform across CTA

    // --- quantize this batch's boxes (threads 0..99) ---
    bool v_me = false;
    if (tid < NBOX) {
        float4 bb = __ldg((const float4*)boxes + b * NBOX + tid);
        int pk = quantize_box(bb, v_me);
        s_box[tid] = v_me ? pk : 0;             // invalid -> x1==x2==0
        if (meta) {
            int cls = __ldg(gt + b * NBOX + tid);
            s_cls[tid] = v_me ? cls : -1;
        }
    }

    // --- bilinear resize (half-pixel centers): src = 2.5*dst + 0.75 ---
    const float* __restrict__ in0 = feat + (size_t)(b * CH + cbas) * (IH * IW);
    const float* __restrict__ in1 = in0 + IH * IW;
    for (int i = tid; i < RH * RW; i += 256) {
        int oy = i / RW, ox = i % RW;
        float sy = 2.5f * (float)oy + 0.75f;    // frac is exactly .75 or .25
        float sx = 2.5f * (float)ox + 0.75f;
        int y0 = (int)sy;  float fy = sy - (float)y0;
        int x0 = (int)sx;  float fx = sx - (float)x0;
        int off = y0 * IW + x0;
        float gx0 = 1.0f - fx, gy0 = 1.0f - fy;
        float a00 = __ldg(in0 + off),      a01 = __ldg(in0 + off + 1);
        float a10 = __ldg(in0 + off + IW), a11 = __ldg(in0 + off + IW + 1);
        float b00 = __ldg(in1 + off),      b01 = __ldg(in1 + off + 1);
        float b10 = __ldg(in1 + off + IW), b11 = __ldg(in1 + off + IW + 1);
        res[0][i] = gy0 * (gx0 * a00 + fx * a01) + fy * (gx0 * a10 + fx * a11);
        res[1][i] = gy0 * (gx0 * b00 + fx * b01) + fy * (gx0 * b10 + fx * b11);
    }
    __syncthreads();

    // --- direct box-average pooling: thread = (plane, box) ---
    if (tid < NBOX * CPB) {
        int n = tid % NBOX;
        int p = tid / NBOX;
        int pk = s_box[n];
        int x1 = pk & 0xFF, y1 = (pk >> 8) & 0xFF;
        int x2 = (pk >> 16) & 0xFF, y2 = (pk >> 24) & 0xFF;
        float out = 0.0f;
        if (x1 < x2) {                          // valid (invalid stored as 0)
            float s = 0.0f;
            const float* r = res[p];
            for (int y = y1; y < y2; y++) {
                float rs = 0.0f;
                for (int x = x1; x < x2; x++) rs += r[y * RW + x];
                s += rs;
            }
            out = s / (float)((y2 - y1) * (x2 - x1));
        }
        s_pool[n][p] = out;
    }
    __syncthreads();

    // --- transposed write: one float2 per box into [B][N][C] ---
    if (tid < NBOX) {
        float2 v2 = make_float2(s_pool[tid][0], s_pool[tid][1]);
        *(float2*)(g_pooled + (size_t)(b * NBOX + tid) * CH + cbas) = v2;
    }

    // --- meta CTA only: counting-sort boxes by class (deterministic) ---
    if (meta) {
        for (int i = tid; i < NCLS; i += 256) s_cnt[i] = 0;
        __syncthreads();
        if (tid < NBOX && s_cls[tid] >= 0)
            atomicAdd(&s_cnt[s_cls[tid]], 1);   // histogram
        __syncthreads();
        if (tid < 19) {                          // group sums (19 x 32)
            int s = 0;
            for (int j = 0; j < 32; j++) {
                int c = tid * 32 + j;
                if (c < NCLS) s += s_cnt[c];
            }
            s_blk[tid] = s;
        }
        __syncthreads();
        if (tid == 0) {
            int r = 0;
            for (int w = 0; w < 19; w++) { int t = s_blk[w]; s_blk[w] = r; r += t; }
            s_blk[19] = r;                      // total valid boxes
        }
        __syncthreads();
        if (tid < 19) {
            int r = s_blk[tid];
            for (int j = 0; j < 32; j++) {
                int c = tid * 32 + j;
                if (c < NCLS) { int t = s_cnt[c]; s_cnt[c] = r; r += t; }  // -> offsets
            }
        }
        __syncthreads();
        for (int i = tid; i < NCLS; i += 256)
            g_start[b * (NCLS + 1) + i] = s_cnt[i];
        if (tid == 0)
            g_start[b * (NCLS + 1) + NCLS] = s_blk[19];
        // scatter: rank = #{m<n with same class} (deterministic ascending order)
        if (tid < NBOX && s_cls[tid] >= 0) {
            int c = s_cls[tid];
            int rank = 0;
            for (int m = 0; m < tid; m++) rank += (s_cls[m] == c);
            g_list[b * NBOX + s_cnt[c] + rank] = tid;
        }
    }
}

// ---------------------------------------------------------------------------
// Kernel 2 (R8/R9-measured best, ~7.7us): scatter-mean, barrier-free.
// One 64-thread group per class (4 groups per CTA); thread = float4
// channel-quad. Empty class (84%): one broadcast load pair + one STG.128 of
// zeros. Non-empty: walk the presorted g_list segment (ascending n ==
// segment_sum order) with float4 gathers. No smem, no __syncthreads.
// ---------------------------------------------------------------------------
__global__ __launch_bounds__(256) void class_mean_kernel(float* __restrict__ out) {
    const int t   = threadIdx.x;
    const int cls = blockIdx.x * 4 + (t >> 6);   // class for this 64-thread group
    const int q   = t & 63;                      // channel quad 0..63
    const int b   = blockIdx.y;
    if (cls >= NCLS) return;

    const int* sp = &g_start[b * (NCLS + 1) + cls];
    int st = __ldg(sp);                          // uniform broadcast within group
    int en = __ldg(sp + 1);

    float4 acc = make_float4(0.0f, 0.0f, 0.0f, 0.0f);
    if (en > st) {
        const float4* __restrict__ pool =
            (const float4*)(g_pooled + (size_t)b * NBOX * CH) + q;
        for (int k = st; k < en; k++) {          // ascending n within class
            int n = __ldg(&g_list[b * NBOX + k]);
            float4 v = __ldg(pool + (size_t)n * (CH / 4));
            acc.x += v.x;  acc.y += v.y;  acc.z += v.z;  acc.w += v.w;
        }
        float inv = 1.0f / (float)(en - st);
        acc.x *= inv;  acc.y *= inv;  acc.z *= inv;  acc.w *= inv;
    }
    ((float4*)(out + (size_t)(b * NCLS + cls) * CH))[q] = acc;
}

// ---------------------------------------------------------------------------
extern "C" void kernel_launch(void* const* d_in, const int* in_sizes, int n_in,
                              void* d_out, int out_size) {
    const float* feat  = (const float*)d_in[0];   // [16,256,100,100] f32
    const float* boxes = (const float*)d_in[1];   // [16,100,4] f32
    const int*   gt    = (const int*)d_in[2];     // [16,100] i32
    float* out = (float*)d_out;                   // [16,599,256] f32

    resize_pool_kernel<<<BATCH * (CH / CPB), 256>>>(feat, boxes, gt);
    dim3 g2((NCLS + 3) / 4, BATCH);               // 150 x 16
    class_mean_kernel<<<g2, 256>>>(out);
}